// round 16
// baseline (speedup 1.0000x reference)
#include <cuda_runtime.h>
#include <cuda_fp16.h>
#include <cstdint>

// fp16 buffers
__device__ __half g_qkv[3*32*256*1024]; // qkv transposed; slot0 reused as tbh
__device__ __half g_xhT[32*1024*256];   // activations [bz][p][k]
__device__ __half g_xh2[32*1024*256];   // h1 transposed
__device__ __half g_whi[6*8*256*256];   // fp16 weights [slot][g][o][k]

typedef unsigned long long u64;
__device__ __forceinline__ uint32_t smem_u32(const void* p) {
    uint32_t a;
    asm("{ .reg .u64 tmp; cvta.to.shared.u64 tmp, %1; cvt.u32.u64 %0, tmp; }"
        : "=r"(a) : "l"(p));
    return a;
}
__device__ __forceinline__ void ldsm4(uint32_t* r, uint32_t addr) {
    asm volatile("ldmatrix.sync.aligned.m8n8.x4.shared.b16 {%0,%1,%2,%3}, [%4];"
        : "=r"(r[0]), "=r"(r[1]), "=r"(r[2]), "=r"(r[3]) : "r"(addr));
}
__device__ __forceinline__ void mma_f16(float* c, const uint32_t* a,
                                        uint32_t b0, uint32_t b1) {
    asm volatile("mma.sync.aligned.m16n8k16.row.col.f32.f16.f16.f32 "
        "{%0,%1,%2,%3}, {%4,%5,%6,%7}, {%8,%9}, {%0,%1,%2,%3};"
        : "+f"(c[0]), "+f"(c[1]), "+f"(c[2]), "+f"(c[3])
        : "r"(a[0]), "r"(a[1]), "r"(a[2]), "r"(a[3]), "r"(b0), "r"(b1));
}
__device__ __forceinline__ void cpasync16(uint32_t saddr, const void* g) {
    asm volatile("cp.async.cg.shared.global [%0], [%1], 16;" :: "r"(saddr), "l"(g));
}
#define CP_COMMIT() asm volatile("cp.async.commit_group;" ::: "memory")
__device__ __forceinline__ __half2 h2u(uint32_t v) {
    __half2 h; *(uint32_t*)&h = v; return h;
}

// ---------------------------------------------------------------------------
// Fused prep: blocks [0,3072) = W fp32->fp16 (slot 4 gets k-permutation
// kc = 2*(k'&127) + (k'>>7)); blocks [3072,11264) = x transpose+convert.
// ---------------------------------------------------------------------------
__global__ __launch_bounds__(256) void prep_kernel(
    const float* __restrict__ w0, const float* __restrict__ w1,
    const float* __restrict__ w2, const float* __restrict__ w3,
    const float* __restrict__ w4, const float* __restrict__ w5,
    __half* __restrict__ whi,
    const float* __restrict__ X, __half* __restrict__ hT)
{
    int b = blockIdx.x;
    int t = threadIdx.x;
    if (b < 3072) {
        const float* srcs[6] = {w0, w1, w2, w3, w4, w5};
        int slot = b >> 9, bx = b & 511;
        size_t idx = ((size_t)bx * 256 + t) * 4;
        u64 hp = 0;
        if (slot == 4) {
            int go = (int)(idx >> 8);
            int kq = (int)(idx & 255);
#pragma unroll
            for (int j = 0; j < 4; j++) {
                int kp = kq + j;
                int kc = 2 * (kp & 127) + (kp >> 7);
                float vv = srcs[4][(size_t)go * 256 + kc];
                hp |= (u64)__half_as_ushort(__float2half_rn(vv)) << (16 * j);
            }
        } else {
            float4 v = *(const float4*)(srcs[slot] + idx);
            float vv[4] = {v.x, v.y, v.z, v.w};
#pragma unroll
            for (int j = 0; j < 4; j++)
                hp |= (u64)__half_as_ushort(__float2half_rn(vv[j])) << (16 * j);
        }
        *(u64*)(whi + (size_t)slot * 524288 + idx) = hp;
        return;
    }
    __shared__ float s[32][33];
    int b2 = b - 3072;
    int pt = b2 & 31, kt = (b2 >> 5) & 7, bz = b2 >> 8;
    const float* Xb = X + ((size_t)bz * 256 + kt * 32) * 1024 + pt * 32;
    int kr = t >> 5, pc = t & 31;
#pragma unroll
    for (int i = 0; i < 4; i++)
        s[kr + i * 8][pc] = Xb[(size_t)(kr + i * 8) * 1024 + pc];
    __syncthreads();
    int pr = t >> 3, kq = t & 7;
    u64 hp = 0;
#pragma unroll
    for (int j = 0; j < 4; j++)
        hp |= (u64)__half_as_ushort(__float2half_rn(s[kq * 4 + j][pr])) << (16 * j);
    size_t o = ((size_t)bz * 1024 + pt * 32 + pr) * 256 + kt * 32 + kq * 4;
    *(u64*)(hT + o) = hp;
}

// ---------------------------------------------------------------------------
// HMMA GEMM, single-pass fp16, cp.async 3-stage ring over 4 k-chunks.
// mode 2: fp16 transposed [bz][p][o] -> Ch (+slot), bias+relu.
// mode 4: skip(fp32 Xskip)+LN -> fp16 k-permuted tbh layout -> Ch.
// mode 5: skip(fp16 tbh via Ch)+LN -> scrambled fp32 -> Cf.
// ---------------------------------------------------------------------------
__global__ __launch_bounds__(256, 2) void hgemm_kernel(
    const __half* __restrict__ whi, const __half* __restrict__ xhT,
    const float* __restrict__ bias, float* __restrict__ Cf,
    __half* __restrict__ Ch, const float* __restrict__ Xskip,
    const float* __restrict__ gam, const float* __restrict__ bet,
    int mode, int relu)
{
    extern __shared__ char smem[];
    uint32_t sbase = smem_u32(smem);

    int t  = threadIdx.x;
    int wi = t >> 5, l = t & 31;
    int wo = wi >> 2, wp = wi & 3;
    int slot = blockIdx.y >> 1;
    int p0 = blockIdx.x * 128, o0 = (blockIdx.y & 1) * 128;
    int bz = blockIdx.z, g = bz & 7;

    const __half* Ahi = whi + (size_t)slot * 524288 + (size_t)g * 65536;
    const __half* Bhi = xhT + (size_t)bz * 262144;

    float acc[4][4][4];
#pragma unroll
    for (int i = 0; i < 4; i++)
#pragma unroll
        for (int j = 0; j < 4; j++)
#pragma unroll
            for (int r = 0; r < 4; r++) acc[i][j][r] = 0.f;

    int rowi[4], kqi[4], swoff[4];
#pragma unroll
    for (int i = 0; i < 4; i++) {
        int v2 = t + i * 256;
        rowi[i] = v2 >> 3; kqi[i] = v2 & 7;
        int off = rowi[i] * 128 + kqi[i] * 16;
        swoff[i] = off ^ ((off >> 3) & 0x70);
    }

    int a_row_l = (l & 15), a_col_l = (l >> 4) << 4;
    int b_quad = l >> 3, b_lr = l & 7;
    int b_row_l = ((b_quad >> 1) << 3) + b_lr;
    int b_col_l = (b_quad & 1) << 4;

#define ISSUE_STAGE(s) do {                                                    \
        int k0_ = (s) * 64;                                                    \
        uint32_t sa_ = sbase + ((s) % 3) * 16384;                              \
        uint32_t sb_ = sbase + 49152 + ((s) % 3) * 16384;                      \
        _Pragma("unroll")                                                      \
        for (int i_ = 0; i_ < 4; i_++) {                                       \
            cpasync16(sa_ + swoff[i_],                                         \
                Ahi + ((size_t)(o0 + rowi[i_]) * 256 + k0_ + kqi[i_] * 8));    \
            cpasync16(sb_ + swoff[i_],                                         \
                Bhi + ((size_t)(p0 + rowi[i_]) * 256 + k0_ + kqi[i_] * 8));    \
        }                                                                      \
        CP_COMMIT();                                                           \
    } while (0)

    ISSUE_STAGE(0);
    ISSUE_STAGE(1);

    for (int s = 0; s < 4; s++) {
        if (s < 3) asm volatile("cp.async.wait_group 1;" ::: "memory");
        else       asm volatile("cp.async.wait_group 0;" ::: "memory");
        __syncthreads();
        if (s < 2) ISSUE_STAGE(s + 2);

        uint32_t sa = sbase + (s % 3) * 16384;
        uint32_t sb = sbase + 49152 + (s % 3) * 16384;
#pragma unroll
        for (int ks = 0; ks < 4; ks++) {
            uint32_t af[4][4];
#pragma unroll
            for (int i = 0; i < 4; i++) {
                int row = wo * 64 + i * 16 + a_row_l;
                int off = row * 128 + ks * 32 + a_col_l;
                ldsm4(af[i], sa + (off ^ ((off >> 3) & 0x70)));
            }
            uint32_t bfr[2][4];
#pragma unroll
            for (int j2 = 0; j2 < 2; j2++) {
                int n2 = wp * 32 + j2 * 16 + b_row_l;
                int off = n2 * 128 + ks * 32 + b_col_l;
                ldsm4(bfr[j2], sb + (off ^ ((off >> 3) & 0x70)));
            }
#pragma unroll
            for (int i = 0; i < 4; i++)
#pragma unroll
                for (int j = 0; j < 4; j++)
                    mma_f16(acc[i][j], af[i], bfr[j >> 1][(j & 1) * 2],
                            bfr[j >> 1][(j & 1) * 2 + 1]);
        }
    }
#undef ISSUE_STAGE

    if (mode == 2) {
        __syncthreads();
        __half* st = (__half*)smem;   // [col][row], stride 136
#pragma unroll
        for (int i = 0; i < 4; i++) {
            int row = wo * 64 + i * 16 + (l >> 2);
            float b0 = bias ? bias[g * 256 + o0 + row]     : 0.f;
            float b8 = bias ? bias[g * 256 + o0 + row + 8] : 0.f;
#pragma unroll
            for (int j = 0; j < 4; j++) {
                int col = wp * 32 + j * 8 + (l & 3) * 2;
                float v0 = acc[i][j][0] + b0, v1 = acc[i][j][1] + b0;
                float v2 = acc[i][j][2] + b8, v3 = acc[i][j][3] + b8;
                if (relu) {
                    v0 = fmaxf(v0, 0.f); v1 = fmaxf(v1, 0.f);
                    v2 = fmaxf(v2, 0.f); v3 = fmaxf(v3, 0.f);
                }
                st[col * 136 + row]           = __float2half_rn(v0);
                st[(col + 1) * 136 + row]     = __float2half_rn(v1);
                st[col * 136 + row + 8]       = __float2half_rn(v2);
                st[(col + 1) * 136 + row + 8] = __float2half_rn(v3);
            }
        }
        __syncthreads();
        __half* Cb = Ch + (size_t)slot * 8388608;
#pragma unroll
        for (int it = 0; it < 8; it++) {
            int idx = t + it * 256;
            int col = idx >> 4, ch = idx & 15;
            uint4 vls = *(const uint4*)(st + col * 136 + ch * 8);
            *(uint4*)(Cb + ((size_t)bz * 1024 + p0 + col) * 256 + o0 + ch * 8) = vls;
        }
        return;
    }

    // ---- modes 4 / 5: fused skip + LayerNorm ----
    __half* sk2 = (__half*)smem;
    if (mode == 5) {
        __syncthreads();
        const __half* Tb = (const __half*)Ch + (size_t)bz * 262144;
#pragma unroll
        for (int it = 0; it < 8; it++) {
            int idx = t + it * 256;
            int pl = idx >> 4, rest = idx & 15;
            int blk = rest >> 3, qd = rest & 7;
            uint4 vls = *(const uint4*)(Tb + (size_t)(p0 + pl) * 256
                                        + blk * 128 + (o0 >> 1) + qd * 8);
            *(uint4*)(sk2 + pl * 136 + blk * 64 + qd * 8) = vls;
        }
        __syncthreads();
    }

    float s1[4][2], s2[4][2];
#pragma unroll
    for (int j = 0; j < 4; j++) { s1[j][0]=0.f; s1[j][1]=0.f; s2[j][0]=0.f; s2[j][1]=0.f; }
    const float* Xb = Xskip ? Xskip + (size_t)bz * 262144 : nullptr;
#pragma unroll
    for (int i = 0; i < 4; i++) {
        int row = o0 + wo * 64 + i * 16 + (l >> 2);
        float b0 = bias ? bias[g * 256 + row]     : 0.f;
        float b8 = bias ? bias[g * 256 + row + 8] : 0.f;
#pragma unroll
        for (int j = 0; j < 4; j++) {
            int col = p0 + wp * 32 + j * 8 + (l & 3) * 2;
            float x00, x01, x10, x11;
            if (mode == 4) {
                float2 x0 = *(const float2*)(Xb + (size_t)row * 1024 + col);
                float2 x1 = *(const float2*)(Xb + (size_t)(row + 8) * 1024 + col);
                x00 = x0.x; x01 = x0.y; x10 = x1.x; x11 = x1.y;
            } else {
                int pl0 = wp * 32 + j * 8 + (l & 3) * 2;
                int ca  = ((row & 1) * 64) + ((row - o0) >> 1);
                x00 = __half2float(sk2[pl0 * 136 + ca]);
                x01 = __half2float(sk2[(pl0 + 1) * 136 + ca]);
                x10 = __half2float(sk2[pl0 * 136 + ca + 4]);
                x11 = __half2float(sk2[(pl0 + 1) * 136 + ca + 4]);
            }
            acc[i][j][0] += b0 + x00;
            acc[i][j][1] += b0 + x01;
            acc[i][j][2] += b8 + x10;
            acc[i][j][3] += b8 + x11;
            s1[j][0] += acc[i][j][0] + acc[i][j][2];
            s1[j][1] += acc[i][j][1] + acc[i][j][3];
            s2[j][0] += acc[i][j][0]*acc[i][j][0] + acc[i][j][2]*acc[i][j][2];
            s2[j][1] += acc[i][j][1]*acc[i][j][1] + acc[i][j][3]*acc[i][j][3];
        }
    }
#pragma unroll
    for (int mk = 4; mk < 32; mk <<= 1) {
#pragma unroll
        for (int j = 0; j < 4; j++) {
            s1[j][0] += __shfl_xor_sync(0xffffffffu, s1[j][0], mk);
            s1[j][1] += __shfl_xor_sync(0xffffffffu, s1[j][1], mk);
            s2[j][0] += __shfl_xor_sync(0xffffffffu, s2[j][0], mk);
            s2[j][1] += __shfl_xor_sync(0xffffffffu, s2[j][1], mk);
        }
    }
    float mu[4][2], rs[4][2];
#pragma unroll
    for (int j = 0; j < 4; j++)
#pragma unroll
        for (int c2 = 0; c2 < 2; c2++) {
            mu[j][c2] = s1[j][c2] * 0.015625f;
            float var = s2[j][c2] * 0.015625f - mu[j][c2] * mu[j][c2];
            rs[j][c2] = rsqrtf(var + 1e-5f);
        }
    __syncthreads();
    float* st = (float*)smem;

    if (mode == 4) {
#pragma unroll
        for (int i = 0; i < 4; i++) {
            int d0 = i * 16 + (l >> 2);
            int row = wo * 64 + d0;
            float g0 = gam[d0], be0 = bet[d0];
            float g8 = gam[d0 + 8], be8 = bet[d0 + 8];
#pragma unroll
            for (int j = 0; j < 4; j++) {
                int col = wp * 32 + j * 8 + (l & 3) * 2;
                st[row * 132 + col]           = (acc[i][j][0] - mu[j][0]) * rs[j][0] * g0 + be0;
                st[row * 132 + col + 1]       = (acc[i][j][1] - mu[j][1]) * rs[j][1] * g0 + be0;
                st[(row + 8) * 132 + col]     = (acc[i][j][2] - mu[j][0]) * rs[j][0] * g8 + be8;
                st[(row + 8) * 132 + col + 1] = (acc[i][j][3] - mu[j][1]) * rs[j][1] * g8 + be8;
            }
        }
        __syncthreads();
        int n = bz >> 3, bx = blockIdx.x, par = o0 >> 7;
#pragma unroll
        for (int it = 0; it < 8; it++) {
            int idx = t + it * 256;
            int row = idx >> 4, ch = idx & 15;
            int o = o0 + row;
            float4 a4 = *(const float4*)(st + row * 132 + ch * 8);
            float4 b4 = *(const float4*)(st + row * 132 + ch * 8 + 4);
            u64 hp = 0;
            hp |= (u64)__half_as_ushort(__float2half_rn(a4.x));
            hp |= (u64)__half_as_ushort(__float2half_rn(a4.y)) << 16;
            hp |= (u64)__half_as_ushort(__float2half_rn(a4.z)) << 32;
            hp |= (u64)__half_as_ushort(__float2half_rn(a4.w)) << 48;
            u64 hq = 0;
            hq |= (u64)__half_as_ushort(__float2half_rn(b4.x));
            hq |= (u64)__half_as_ushort(__float2half_rn(b4.y)) << 16;
            hq |= (u64)__half_as_ushort(__float2half_rn(b4.z)) << 32;
            hq |= (u64)__half_as_ushort(__float2half_rn(b4.w)) << 48;
            int pp = ((o >> 6) & 1) * 512 + g * 64 + (o & 63);
            __half* dst = Ch + ((size_t)(n * 8 + bx) * 1024 + pp) * 256
                          + par * 128 + ch * 8;
            *(u64*)(dst)     = hp;
            *(u64*)(dst + 4) = hq;
        }
        return;
    }

    // mode 5: stage [col][row] stride 132, then scrambled fp32 out
#pragma unroll
    for (int i = 0; i < 4; i++) {
        int d0 = i * 16 + (l >> 2);
        int row = wo * 64 + d0;
        float g0 = gam[d0], be0 = bet[d0];
        float g8 = gam[d0 + 8], be8 = bet[d0 + 8];
#pragma unroll
        for (int j = 0; j < 4; j++) {
            int col = wp * 32 + j * 8 + (l & 3) * 2;
            st[col * 132 + row]           = (acc[i][j][0] - mu[j][0]) * rs[j][0] * g0 + be0;
            st[(col + 1) * 132 + row]     = (acc[i][j][1] - mu[j][1]) * rs[j][1] * g0 + be0;
            st[col * 132 + row + 8]       = (acc[i][j][2] - mu[j][0]) * rs[j][0] * g8 + be8;
            st[(col + 1) * 132 + row + 8] = (acc[i][j][3] - mu[j][1]) * rs[j][1] * g8 + be8;
        }
    }
    __syncthreads();
    int n = bz >> 3;
#pragma unroll
    for (int it = 0; it < 16; it++) {
        int idx = t + it * 256;
        int col = idx >> 5, quad = idx & 31;
        float4 vls = *(const float4*)(st + col * 132 + quad * 4);
        int o = o0 + quad * 4;
        size_t ga = ((size_t)(n * 1024 + p0 + col) * 2048)
                    + (size_t)(o >> 6) * 512 + g * 64 + (o & 63);
        *(float4*)(Cf + ga) = vls;
    }
}

// ---------------------------------------------------------------------------
// Windowed attention; fused rel+score loop, direct coalesced epilogue.
// ---------------------------------------------------------------------------
#define EPS_H 72
#define HPS_H 576
#define QPS_H 576
#define SK_H (40*HPS_H)
#define SQ_H (16*QPS_H)
#define REL_H (12*EPS_H)
#define ATTN_SMEM_B ((SK_H*2 + SQ_H + REL_H*2) * 2)

__global__ __launch_bounds__(512, 2) void attn_kernel(
    const __half* __restrict__ q, const __half* __restrict__ k,
    const __half* __restrict__ v, const float* __restrict__ hm,
    const float* __restrict__ wmm, __half* __restrict__ avhT)
{
    extern __shared__ __half smemh[];
    __half* sk  = smemh;
    __half* sv  = sk + SK_H;
    __half* sq  = sv + SK_H;
    __half* srh = sq + SQ_H;
    __half* srw = srh + REL_H;
    __half2* attd = (__half2*)sk;

    int t  = threadIdx.x;
    int w0 = blockIdx.x << 3;
    int h0 = blockIdx.y << 1;
    int nm = blockIdx.z;
    int n  = nm >> 2, m = nm & 3;

    for (int idx = t; idx < 5120; idx += 512) {
        int d4  = idx & 15;
        int e   = (idx >> 4) & 7;
        int pos = idx >> 7;
        int r = pos / 10, c = pos % 10;
        int h2 = h0 + r - 1, w2 = w0 + c - 1;
        u64 kv = 0, vv = 0;
        if (h2 >= 0 && h2 < 32 && w2 >= 0 && w2 < 32) {
            size_t gi = (((size_t)(n * 8 + e) * 1024) + h2 * 32 + w2) * 256
                        + m * 64 + d4 * 4;
            kv = *(const u64*)(k + gi);
            vv = *(const u64*)(v + gi);
        }
        int si = pos * HPS_H + e * EPS_H + d4 * 4;
        *(u64*)(sk + si) = kv;
        *(u64*)(sv + si) = vv;
    }
    for (int idx = t; idx < 2048; idx += 512) {
        int d4  = idx & 15;
        int gq  = (idx >> 4) & 7;
        int pix = idx >> 7;
        int p = (h0 + (pix >> 3)) * 32 + w0 + (pix & 7);
        size_t gi = (((size_t)(n * 8 + gq) * 1024) + p) * 256 + m * 64 + d4 * 4;
        *(u64*)(sq + pix * QPS_H + gq * EPS_H + d4 * 4) = *(const u64*)(q + gi);
    }
    for (int idx = t; idx < 768; idx += 512) {
        int d  = idx & 63;
        int ei = idx >> 6;
        int e  = ei / 3, i = ei % 3;
        srh[ei * EPS_H + d] = __float2half_rn(hm [((e * 256 + m * 64 + d) * 3) + i]);
        srw[ei * EPS_H + d] = __float2half_rn(wmm[((e * 256 + m * 64 + d) * 3) + i]);
    }
    __syncthreads();

    int wi = t >> 5, l = t & 31;
    int g  = l >> 2, e0 = l & 3;
    int pr = wi >> 3, cc = (wi & 7) + 1;
    const __half* sqw = sq + wi * QPS_H + g * EPS_H;
    int eoff = e0 * EPS_H;

    int posoff[9];
#pragma unroll
    for (int i = 0; i < 3; i++)
#pragma unroll
        for (int j = 0; j < 3; j++)
            posoff[i * 3 + j] = ((pr + i) * 10 + cc - 1 + j) * HPS_H;

    __half2 z2 = __float2half2_rn(0.f);

    // ---- fused q.rel + scores: one pass over d, single q load per d8 ----
    __half2 hA2[3], hB2[3], cA2[9], cB2[9];
#pragma unroll
    for (int u = 0; u < 3; u++) { hA2[u] = z2; hB2[u] = z2; }
#pragma unroll
    for (int u = 0; u < 9; u++) { cA2[u] = z2; cB2[u] = z2; }
#pragma unroll
    for (int d8 = 0; d8 < 8; d8++) {
        int dd = d8 * 8;
        uint4 qv = *(const uint4*)(sqw + dd);
#pragma unroll
        for (int u = 0; u < 3; u++) {
            uint4 r4 = *(const uint4*)(srh + (e0 * 3 + u) * EPS_H + dd);
            uint4 s4 = *(const uint4*)(srw + (e0 * 3 + u) * EPS_H + dd);
            hA2[u] = __hfma2(h2u(qv.x), h2u(r4.x), hA2[u]);
            hA2[u] = __hfma2(h2u(qv.y), h2u(r4.y), hA2[u]);
            hA2[u] = __hfma2(h2u(qv.z), h2u(r4.z), hA2[u]);
            hA2[u] = __hfma2(h2u(qv.w), h2u(r4.w), hA2[u]);
            hB2[u] = __hfma2(h2u(qv.x), h2u(s4.x), hB2[u]);
            hB2[u] = __hfma2(h2u(qv.y), h2u(s4.y), hB2[u]);
            hB2[u] = __hfma2(h2u(qv.z), h2u(s4.z), hB2[u]);
            hB2[u] = __hfma2(h2u(qv.w), h2u(s4.w), hB2[u]);
        }
#pragma unroll
        for (int u = 0; u < 9; u++) {
            const __half* kp = sk + posoff[u] + eoff + dd;
            uint4 ka = *(const uint4*)(kp);
            uint4 kc = *(const uint4*)(kp + 4 * EPS_H);
            cA2[u] = __hfma2(h2u(qv.x), h2u(ka.x), cA2[u]);
            cA2[u] = __hfma2(h2u(qv.y), h2u(ka.y), cA2[u]);
            cA2[u] = __hfma2(h2u(qv.z), h2u(ka.z), cA2[u]);
            cA2[u] = __hfma2(h2u(qv.w), h2u(ka.w), cA2[u]);
            cB2[u] = __hfma2(h2u(qv.x), h2u(kc.x), cB2[u]);
            cB2[u] = __hfma2(h2u(qv.y), h2u(kc.y), cB2[u]);
            cB2[u] = __hfma2(h2u(qv.z), h2u(kc.z), cB2[u]);
            cB2[u] = __hfma2(h2u(qv.w), h2u(kc.w), cB2[u]);
        }
    }
    float qrA[3], qrB[3];
#pragma unroll
    for (int u = 0; u < 3; u++) {
        float2 fa = __half22float2(hA2[u]), fb = __half22float2(hB2[u]);
        qrA[u] = fa.x + fa.y; qrB[u] = fb.x + fb.y;
    }
    float sA[9], sB[9];
#pragma unroll
    for (int u = 0; u < 9; u++) {
        float2 fa = __half22float2(cA2[u]), fb = __half22float2(cB2[u]);
        sA[u] = fa.x + fa.y + qrA[u / 3];
        sB[u] = fb.x + fb.y + qrB[u % 3];
    }

    float mx = -1e30f;
#pragma unroll
    for (int u = 0; u < 9; u++) mx = fmaxf(mx, fmaxf(sA[u], sB[u]));
    mx = fmaxf(mx, __shfl_xor_sync(0xffffffffu, mx, 1));
    mx = fmaxf(mx, __shfl_xor_sync(0xffffffffu, mx, 2));
    float sum = 0.f;
#pragma unroll
    for (int u = 0; u < 9; u++) {
        sA[u] = __expf(sA[u] - mx);
        sB[u] = __expf(sB[u] - mx);
        sum += sA[u] + sB[u];
    }
    sum += __shfl_xor_sync(0xffffffffu, sum, 1);
    sum += __shfl_xor_sync(0xffffffffu, sum, 2);
    float inv = 1.f / sum;

    __syncthreads();   // all warps done reading sk (k) before attd overlay

    __half2* awT = attd + wi * 576;
#pragma unroll
    for (int u = 0; u < 9; u++) {
        awT[((e0 * 9 + u) * 8 + g)]       = __float2half2_rn(sA[u] * inv);
        awT[(((e0 + 4) * 9 + u) * 8 + g)] = __float2half2_rn(sB[u] * inv);
    }
    __syncwarp();

    __half2 acc2[8];
#pragma unroll
    for (int gg = 0; gg < 8; gg++) acc2[gg] = z2;
#pragma unroll 1
    for (int e = 0; e < 8; e++) {
        const __half* vb = sv + e * EPS_H + 2 * l;
#pragma unroll
        for (int nb = 0; nb < 9; nb++) {
            __half2 v2 = *(const __half2*)(vb + posoff[nb]);
            const uint4* wp2 = (const uint4*)(awT + (e * 9 + nb) * 8);
            uint4 wa = wp2[0], wb = wp2[1];
            acc2[0] = __hfma2(h2u(wa.x), v2, acc2[0]);
            acc2[1] = __hfma2(h2u(wa.y), v2, acc2[1]);
            acc2[2] = __hfma2(h2u(wa.z), v2, acc2[2]);
            acc2[3] = __hfma2(h2u(wa.w), v2, acc2[3]);
            acc2[4] = __hfma2(h2u(wb.x), v2, acc2[4]);
            acc2[5] = __hfma2(h2u(wb.y), v2, acc2[5]);
            acc2[6] = __hfma2(h2u(wb.z), v2, acc2[6]);
            acc2[7] = __hfma2(h2u(wb.w), v2, acc2[7]);
        }
    }

    // ---- direct coalesced store: per g, warp covers 128 contiguous bytes ----
    {
        int p = (h0 + (wi >> 3)) * 32 + w0 + (wi & 7);
        __half* ob = avhT + (((size_t)(n * 8) * 1024) + p) * 256 + m * 64 + 2 * l;
#pragma unroll
        for (int gg = 0; gg < 8; gg++)
            *(__half2*)(ob + (size_t)gg * 262144) = acc2[gg];
    }
}

// ---------------------------------------------------------------------------
extern "C" void kernel_launch(void* const* d_in, const int* in_sizes, int n_in,
                              void* d_out, int out_size)
{
    (void)in_sizes; (void)n_in; (void)out_size;
    const float* x     = (const float*)d_in[0];
    const float* wq    = (const float*)d_in[1];
    const float* wk    = (const float*)d_in[2];
    const float* wv    = (const float*)d_in[3];
    const float* hm    = (const float*)d_in[4];
    const float* wm    = (const float*)d_in[5];
    const float* wconv = (const float*)d_in[6];
    const float* bconv = (const float*)d_in[7];
    const float* wf1   = (const float*)d_in[8];
    const float* bf1   = (const float*)d_in[9];
    const float* wf2   = (const float*)d_in[10];
    const float* bf2   = (const float*)d_in[11];
    const float* g1    = (const float*)d_in[12];
    const float* b1    = (const float*)d_in[13];
    const float* g2    = (const float*)d_in[14];
    const float* b2    = (const float*)d_in[15];

    __half *qkvh, *xhT, *xh2, *whi;
    cudaGetSymbolAddress((void**)&qkvh, g_qkv);
    cudaGetSymbolAddress((void**)&xhT,  g_xhT);
    cudaGetSymbolAddress((void**)&xh2,  g_xh2);
    cudaGetSymbolAddress((void**)&whi,  g_whi);

    cudaFuncSetAttribute(attn_kernel,
                         cudaFuncAttributeMaxDynamicSharedMemorySize, ATTN_SMEM_B);
    const int GEMM_SMEM = 98304;
    cudaFuncSetAttribute(hgemm_kernel,
                         cudaFuncAttributeMaxDynamicSharedMemorySize, GEMM_SMEM);

    const size_t WS = 524288;        // per-slot W elements
    const size_t QS = 8388608;       // per-slot qkv halves

    // fused weight-convert (slot4 k-permuted) + x transpose-convert
    prep_kernel<<<11264, 256>>>(wq, wk, wv, wconv, wf1, wf2, whi, x, xhT);

    // fused q/k/v GEMM -> fp16 transposed [bz][p][c] per slot
    hgemm_kernel<<<dim3(8, 6, 32), 256, GEMM_SMEM>>>(whi, xhT, nullptr,
        nullptr, qkvh, nullptr, nullptr, nullptr, 2, 0);

    attn_kernel<<<dim3(4, 16, 16), 512, ATTN_SMEM_B>>>(qkvh, qkvh + QS, qkvh + 2 * QS,
                                                       hm, wm, xhT);

    // w_conv GEMM: skip(x)+LN1 -> fp16 k-permuted tbh (into qkv slot 0)
    hgemm_kernel<<<dim3(8, 2, 32), 256, GEMM_SMEM>>>(whi + 3*WS, xhT, bconv,
        nullptr, qkvh, x, g1, b1, 4, 0);

    // f1 GEMM (relu, permuted weights) reads tbh -> fp16 transposed xh2
    hgemm_kernel<<<dim3(8, 2, 32), 256, GEMM_SMEM>>>(whi + 4*WS, qkvh, bf1,
        nullptr, xh2, nullptr, nullptr, nullptr, 2, 1);

    // f2 GEMM: skip(tbh fp16)+LN2 -> scrambled fp32 d_out
    hgemm_kernel<<<dim3(8, 2, 32), 256, GEMM_SMEM>>>(whi + 5*WS, xh2, bf2,
        (float*)d_out, qkvh, nullptr, g2, b2, 5, 0);
}

// round 17
// speedup vs baseline: 1.0235x; 1.0235x over previous
#include <cuda_runtime.h>
#include <cuda_fp16.h>
#include <cstdint>

// fp16 buffers
__device__ __half g_qkv[3*32*256*1024]; // qkv transposed; slot0 reused as tbh
__device__ __half g_xhT[32*1024*256];   // activations [bz][p][k]
__device__ __half g_xh2[32*1024*256];   // h1 transposed
__device__ __half g_whi[6*8*256*256];   // fp16 weights [slot][g][o][k]

typedef unsigned long long u64;
__device__ __forceinline__ uint32_t smem_u32(const void* p) {
    uint32_t a;
    asm("{ .reg .u64 tmp; cvta.to.shared.u64 tmp, %1; cvt.u32.u64 %0, tmp; }"
        : "=r"(a) : "l"(p));
    return a;
}
__device__ __forceinline__ void ldsm4(uint32_t* r, uint32_t addr) {
    asm volatile("ldmatrix.sync.aligned.m8n8.x4.shared.b16 {%0,%1,%2,%3}, [%4];"
        : "=r"(r[0]), "=r"(r[1]), "=r"(r[2]), "=r"(r[3]) : "r"(addr));
}
__device__ __forceinline__ void mma_f16(float* c, const uint32_t* a,
                                        uint32_t b0, uint32_t b1) {
    asm volatile("mma.sync.aligned.m16n8k16.row.col.f32.f16.f16.f32 "
        "{%0,%1,%2,%3}, {%4,%5,%6,%7}, {%8,%9}, {%0,%1,%2,%3};"
        : "+f"(c[0]), "+f"(c[1]), "+f"(c[2]), "+f"(c[3])
        : "r"(a[0]), "r"(a[1]), "r"(a[2]), "r"(a[3]), "r"(b0), "r"(b1));
}
__device__ __forceinline__ void cpasync16(uint32_t saddr, const void* g) {
    asm volatile("cp.async.cg.shared.global [%0], [%1], 16;" :: "r"(saddr), "l"(g));
}
#define CP_COMMIT() asm volatile("cp.async.commit_group;" ::: "memory")
__device__ __forceinline__ __half2 h2u(uint32_t v) {
    __half2 h; *(uint32_t*)&h = v; return h;
}

// ---------------------------------------------------------------------------
// Fused prep: blocks [0,3072) = W fp32->fp16 (slot 4 gets k-permutation
// kc = 2*(k'&127) + (k'>>7)); blocks [3072,11264) = x transpose+convert.
// ---------------------------------------------------------------------------
__global__ __launch_bounds__(256) void prep_kernel(
    const float* __restrict__ w0, const float* __restrict__ w1,
    const float* __restrict__ w2, const float* __restrict__ w3,
    const float* __restrict__ w4, const float* __restrict__ w5,
    __half* __restrict__ whi,
    const float* __restrict__ X, __half* __restrict__ hT)
{
    int b = blockIdx.x;
    int t = threadIdx.x;
    if (b < 3072) {
        const float* srcs[6] = {w0, w1, w2, w3, w4, w5};
        int slot = b >> 9, bx = b & 511;
        size_t idx = ((size_t)bx * 256 + t) * 4;
        u64 hp = 0;
        if (slot == 4) {
            int go = (int)(idx >> 8);
            int kq = (int)(idx & 255);
#pragma unroll
            for (int j = 0; j < 4; j++) {
                int kp = kq + j;
                int kc = 2 * (kp & 127) + (kp >> 7);
                float vv = srcs[4][(size_t)go * 256 + kc];
                hp |= (u64)__half_as_ushort(__float2half_rn(vv)) << (16 * j);
            }
        } else {
            float4 v = *(const float4*)(srcs[slot] + idx);
            float vv[4] = {v.x, v.y, v.z, v.w};
#pragma unroll
            for (int j = 0; j < 4; j++)
                hp |= (u64)__half_as_ushort(__float2half_rn(vv[j])) << (16 * j);
        }
        *(u64*)(whi + (size_t)slot * 524288 + idx) = hp;
        return;
    }
    __shared__ float s[32][33];
    int b2 = b - 3072;
    int pt = b2 & 31, kt = (b2 >> 5) & 7, bz = b2 >> 8;
    const float* Xb = X + ((size_t)bz * 256 + kt * 32) * 1024 + pt * 32;
    int kr = t >> 5, pc = t & 31;
#pragma unroll
    for (int i = 0; i < 4; i++)
        s[kr + i * 8][pc] = Xb[(size_t)(kr + i * 8) * 1024 + pc];
    __syncthreads();
    int pr = t >> 3, kq = t & 7;
    u64 hp = 0;
#pragma unroll
    for (int j = 0; j < 4; j++)
        hp |= (u64)__half_as_ushort(__float2half_rn(s[kq * 4 + j][pr])) << (16 * j);
    size_t o = ((size_t)bz * 1024 + pt * 32 + pr) * 256 + kt * 32 + kq * 4;
    *(u64*)(hT + o) = hp;
}

// ---------------------------------------------------------------------------
// HMMA GEMM, single-pass fp16, cp.async 3-stage ring over 4 k-chunks.
// mode 2: fp16 transposed [bz][p][o] -> Ch (+slot), bias+relu.
// mode 4: skip(fp32 Xskip)+LN -> fp16 k-permuted tbh layout -> Ch.
// mode 5: skip(fp16 tbh via Ch)+LN -> scrambled fp32 -> Cf.
// ---------------------------------------------------------------------------
__global__ __launch_bounds__(256, 2) void hgemm_kernel(
    const __half* __restrict__ whi, const __half* __restrict__ xhT,
    const float* __restrict__ bias, float* __restrict__ Cf,
    __half* __restrict__ Ch, const float* __restrict__ Xskip,
    const float* __restrict__ gam, const float* __restrict__ bet,
    int mode, int relu)
{
    extern __shared__ char smem[];
    uint32_t sbase = smem_u32(smem);

    int t  = threadIdx.x;
    int wi = t >> 5, l = t & 31;
    int wo = wi >> 2, wp = wi & 3;
    int slot = blockIdx.y >> 1;
    int p0 = blockIdx.x * 128, o0 = (blockIdx.y & 1) * 128;
    int bz = blockIdx.z, g = bz & 7;

    const __half* Ahi = whi + (size_t)slot * 524288 + (size_t)g * 65536;
    const __half* Bhi = xhT + (size_t)bz * 262144;

    float acc[4][4][4];
#pragma unroll
    for (int i = 0; i < 4; i++)
#pragma unroll
        for (int j = 0; j < 4; j++)
#pragma unroll
            for (int r = 0; r < 4; r++) acc[i][j][r] = 0.f;

    int rowi[4], kqi[4], swoff[4];
#pragma unroll
    for (int i = 0; i < 4; i++) {
        int v2 = t + i * 256;
        rowi[i] = v2 >> 3; kqi[i] = v2 & 7;
        int off = rowi[i] * 128 + kqi[i] * 16;
        swoff[i] = off ^ ((off >> 3) & 0x70);
    }

    int a_row_l = (l & 15), a_col_l = (l >> 4) << 4;
    int b_quad = l >> 3, b_lr = l & 7;
    int b_row_l = ((b_quad >> 1) << 3) + b_lr;
    int b_col_l = (b_quad & 1) << 4;

#define ISSUE_STAGE(s) do {                                                    \
        int k0_ = (s) * 64;                                                    \
        uint32_t sa_ = sbase + ((s) % 3) * 16384;                              \
        uint32_t sb_ = sbase + 49152 + ((s) % 3) * 16384;                      \
        _Pragma("unroll")                                                      \
        for (int i_ = 0; i_ < 4; i_++) {                                       \
            cpasync16(sa_ + swoff[i_],                                         \
                Ahi + ((size_t)(o0 + rowi[i_]) * 256 + k0_ + kqi[i_] * 8));    \
            cpasync16(sb_ + swoff[i_],                                         \
                Bhi + ((size_t)(p0 + rowi[i_]) * 256 + k0_ + kqi[i_] * 8));    \
        }                                                                      \
        CP_COMMIT();                                                           \
    } while (0)

    ISSUE_STAGE(0);
    ISSUE_STAGE(1);

    for (int s = 0; s < 4; s++) {
        if (s < 3) asm volatile("cp.async.wait_group 1;" ::: "memory");
        else       asm volatile("cp.async.wait_group 0;" ::: "memory");
        __syncthreads();
        if (s < 2) ISSUE_STAGE(s + 2);

        uint32_t sa = sbase + (s % 3) * 16384;
        uint32_t sb = sbase + 49152 + (s % 3) * 16384;
#pragma unroll
        for (int ks = 0; ks < 4; ks++) {
            uint32_t af[4][4];
#pragma unroll
            for (int i = 0; i < 4; i++) {
                int row = wo * 64 + i * 16 + a_row_l;
                int off = row * 128 + ks * 32 + a_col_l;
                ldsm4(af[i], sa + (off ^ ((off >> 3) & 0x70)));
            }
            uint32_t bfr[2][4];
#pragma unroll
            for (int j2 = 0; j2 < 2; j2++) {
                int n2 = wp * 32 + j2 * 16 + b_row_l;
                int off = n2 * 128 + ks * 32 + b_col_l;
                ldsm4(bfr[j2], sb + (off ^ ((off >> 3) & 0x70)));
            }
#pragma unroll
            for (int i = 0; i < 4; i++)
#pragma unroll
                for (int j = 0; j < 4; j++)
                    mma_f16(acc[i][j], af[i], bfr[j >> 1][(j & 1) * 2],
                            bfr[j >> 1][(j & 1) * 2 + 1]);
        }
    }
#undef ISSUE_STAGE

    if (mode == 2) {
        __syncthreads();
        __half* st = (__half*)smem;   // [col][row], stride 136
#pragma unroll
        for (int i = 0; i < 4; i++) {
            int row = wo * 64 + i * 16 + (l >> 2);
            float b0 = bias ? bias[g * 256 + o0 + row]     : 0.f;
            float b8 = bias ? bias[g * 256 + o0 + row + 8] : 0.f;
#pragma unroll
            for (int j = 0; j < 4; j++) {
                int col = wp * 32 + j * 8 + (l & 3) * 2;
                float v0 = acc[i][j][0] + b0, v1 = acc[i][j][1] + b0;
                float v2 = acc[i][j][2] + b8, v3 = acc[i][j][3] + b8;
                if (relu) {
                    v0 = fmaxf(v0, 0.f); v1 = fmaxf(v1, 0.f);
                    v2 = fmaxf(v2, 0.f); v3 = fmaxf(v3, 0.f);
                }
                st[col * 136 + row]           = __float2half_rn(v0);
                st[(col + 1) * 136 + row]     = __float2half_rn(v1);
                st[col * 136 + row + 8]       = __float2half_rn(v2);
                st[(col + 1) * 136 + row + 8] = __float2half_rn(v3);
            }
        }
        __syncthreads();
        __half* Cb = Ch + (size_t)slot * 8388608;
#pragma unroll
        for (int it = 0; it < 8; it++) {
            int idx = t + it * 256;
            int col = idx >> 4, ch = idx & 15;
            uint4 vls = *(const uint4*)(st + col * 136 + ch * 8);
            *(uint4*)(Cb + ((size_t)bz * 1024 + p0 + col) * 256 + o0 + ch * 8) = vls;
        }
        return;
    }

    // ---- modes 4 / 5: fused skip + LayerNorm ----
    __half* sk2 = (__half*)smem;
    if (mode == 5) {
        __syncthreads();
        const __half* Tb = (const __half*)Ch + (size_t)bz * 262144;
#pragma unroll
        for (int it = 0; it < 8; it++) {
            int idx = t + it * 256;
            int pl = idx >> 4, rest = idx & 15;
            int blk = rest >> 3, qd = rest & 7;
            uint4 vls = *(const uint4*)(Tb + (size_t)(p0 + pl) * 256
                                        + blk * 128 + (o0 >> 1) + qd * 8);
            *(uint4*)(sk2 + pl * 136 + blk * 64 + qd * 8) = vls;
        }
        __syncthreads();
    }

    float s1[4][2], s2[4][2];
#pragma unroll
    for (int j = 0; j < 4; j++) { s1[j][0]=0.f; s1[j][1]=0.f; s2[j][0]=0.f; s2[j][1]=0.f; }
    const float* Xb = Xskip ? Xskip + (size_t)bz * 262144 : nullptr;
#pragma unroll
    for (int i = 0; i < 4; i++) {
        int row = o0 + wo * 64 + i * 16 + (l >> 2);
        float b0 = bias ? bias[g * 256 + row]     : 0.f;
        float b8 = bias ? bias[g * 256 + row + 8] : 0.f;
#pragma unroll
        for (int j = 0; j < 4; j++) {
            int col = p0 + wp * 32 + j * 8 + (l & 3) * 2;
            float x00, x01, x10, x11;
            if (mode == 4) {
                float2 x0 = *(const float2*)(Xb + (size_t)row * 1024 + col);
                float2 x1 = *(const float2*)(Xb + (size_t)(row + 8) * 1024 + col);
                x00 = x0.x; x01 = x0.y; x10 = x1.x; x11 = x1.y;
            } else {
                int pl0 = wp * 32 + j * 8 + (l & 3) * 2;
                int ca  = ((row & 1) * 64) + ((row - o0) >> 1);
                x00 = __half2float(sk2[pl0 * 136 + ca]);
                x01 = __half2float(sk2[(pl0 + 1) * 136 + ca]);
                x10 = __half2float(sk2[pl0 * 136 + ca + 4]);
                x11 = __half2float(sk2[(pl0 + 1) * 136 + ca + 4]);
            }
            acc[i][j][0] += b0 + x00;
            acc[i][j][1] += b0 + x01;
            acc[i][j][2] += b8 + x10;
            acc[i][j][3] += b8 + x11;
            s1[j][0] += acc[i][j][0] + acc[i][j][2];
            s1[j][1] += acc[i][j][1] + acc[i][j][3];
            s2[j][0] += acc[i][j][0]*acc[i][j][0] + acc[i][j][2]*acc[i][j][2];
            s2[j][1] += acc[i][j][1]*acc[i][j][1] + acc[i][j][3]*acc[i][j][3];
        }
    }
#pragma unroll
    for (int mk = 4; mk < 32; mk <<= 1) {
#pragma unroll
        for (int j = 0; j < 4; j++) {
            s1[j][0] += __shfl_xor_sync(0xffffffffu, s1[j][0], mk);
            s1[j][1] += __shfl_xor_sync(0xffffffffu, s1[j][1], mk);
            s2[j][0] += __shfl_xor_sync(0xffffffffu, s2[j][0], mk);
            s2[j][1] += __shfl_xor_sync(0xffffffffu, s2[j][1], mk);
        }
    }
    float mu[4][2], rs[4][2];
#pragma unroll
    for (int j = 0; j < 4; j++)
#pragma unroll
        for (int c2 = 0; c2 < 2; c2++) {
            mu[j][c2] = s1[j][c2] * 0.015625f;
            float var = s2[j][c2] * 0.015625f - mu[j][c2] * mu[j][c2];
            rs[j][c2] = rsqrtf(var + 1e-5f);
        }
    __syncthreads();
    float* st = (float*)smem;

    if (mode == 4) {
#pragma unroll
        for (int i = 0; i < 4; i++) {
            int d0 = i * 16 + (l >> 2);
            int row = wo * 64 + d0;
            float g0 = gam[d0], be0 = bet[d0];
            float g8 = gam[d0 + 8], be8 = bet[d0 + 8];
#pragma unroll
            for (int j = 0; j < 4; j++) {
                int col = wp * 32 + j * 8 + (l & 3) * 2;
                st[row * 132 + col]           = (acc[i][j][0] - mu[j][0]) * rs[j][0] * g0 + be0;
                st[row * 132 + col + 1]       = (acc[i][j][1] - mu[j][1]) * rs[j][1] * g0 + be0;
                st[(row + 8) * 132 + col]     = (acc[i][j][2] - mu[j][0]) * rs[j][0] * g8 + be8;
                st[(row + 8) * 132 + col + 1] = (acc[i][j][3] - mu[j][1]) * rs[j][1] * g8 + be8;
            }
        }
        __syncthreads();
        int n = bz >> 3, bx = blockIdx.x, par = o0 >> 7;
#pragma unroll
        for (int it = 0; it < 8; it++) {
            int idx = t + it * 256;
            int row = idx >> 4, ch = idx & 15;
            int o = o0 + row;
            float4 a4 = *(const float4*)(st + row * 132 + ch * 8);
            float4 b4 = *(const float4*)(st + row * 132 + ch * 8 + 4);
            u64 hp = 0;
            hp |= (u64)__half_as_ushort(__float2half_rn(a4.x));
            hp |= (u64)__half_as_ushort(__float2half_rn(a4.y)) << 16;
            hp |= (u64)__half_as_ushort(__float2half_rn(a4.z)) << 32;
            hp |= (u64)__half_as_ushort(__float2half_rn(a4.w)) << 48;
            u64 hq = 0;
            hq |= (u64)__half_as_ushort(__float2half_rn(b4.x));
            hq |= (u64)__half_as_ushort(__float2half_rn(b4.y)) << 16;
            hq |= (u64)__half_as_ushort(__float2half_rn(b4.z)) << 32;
            hq |= (u64)__half_as_ushort(__float2half_rn(b4.w)) << 48;
            int pp = ((o >> 6) & 1) * 512 + g * 64 + (o & 63);
            __half* dst = Ch + ((size_t)(n * 8 + bx) * 1024 + pp) * 256
                          + par * 128 + ch * 8;
            *(u64*)(dst)     = hp;
            *(u64*)(dst + 4) = hq;
        }
        return;
    }

    // mode 5: stage [col][row] stride 132, then scrambled fp32 out
#pragma unroll
    for (int i = 0; i < 4; i++) {
        int d0 = i * 16 + (l >> 2);
        int row = wo * 64 + d0;
        float g0 = gam[d0], be0 = bet[d0];
        float g8 = gam[d0 + 8], be8 = bet[d0 + 8];
#pragma unroll
        for (int j = 0; j < 4; j++) {
            int col = wp * 32 + j * 8 + (l & 3) * 2;
            st[col * 132 + row]           = (acc[i][j][0] - mu[j][0]) * rs[j][0] * g0 + be0;
            st[(col + 1) * 132 + row]     = (acc[i][j][1] - mu[j][1]) * rs[j][1] * g0 + be0;
            st[col * 132 + row + 8]       = (acc[i][j][2] - mu[j][0]) * rs[j][0] * g8 + be8;
            st[(col + 1) * 132 + row + 8] = (acc[i][j][3] - mu[j][1]) * rs[j][1] * g8 + be8;
        }
    }
    __syncthreads();
    int n = bz >> 3;
#pragma unroll
    for (int it = 0; it < 16; it++) {
        int idx = t + it * 256;
        int col = idx >> 5, quad = idx & 31;
        float4 vls = *(const float4*)(st + col * 132 + quad * 4);
        int o = o0 + quad * 4;
        size_t ga = ((size_t)(n * 1024 + p0 + col) * 2048)
                    + (size_t)(o >> 6) * 512 + g * 64 + (o & 63);
        *(float4*)(Cf + ga) = vls;
    }
}

// ---------------------------------------------------------------------------
// Windowed attention; R15 separate rel/score loops + direct coalesced
// epilogue (no staging). fp16 smem + HFMA2, 2 CTAs/SM.
// ---------------------------------------------------------------------------
#define EPS_H 72
#define HPS_H 576
#define QPS_H 576
#define SK_H (40*HPS_H)
#define SQ_H (16*QPS_H)
#define REL_H (12*EPS_H)
#define ATTN_SMEM_B ((SK_H*2 + SQ_H + REL_H*2) * 2)

__global__ __launch_bounds__(512, 2) void attn_kernel(
    const __half* __restrict__ q, const __half* __restrict__ k,
    const __half* __restrict__ v, const float* __restrict__ hm,
    const float* __restrict__ wmm, __half* __restrict__ avhT)
{
    extern __shared__ __half smemh[];
    __half* sk  = smemh;
    __half* sv  = sk + SK_H;
    __half* sq  = sv + SK_H;
    __half* srh = sq + SQ_H;
    __half* srw = srh + REL_H;
    __half2* attd = (__half2*)sk;

    int t  = threadIdx.x;
    int w0 = blockIdx.x << 3;
    int h0 = blockIdx.y << 1;
    int nm = blockIdx.z;
    int n  = nm >> 2, m = nm & 3;

    for (int idx = t; idx < 5120; idx += 512) {
        int d4  = idx & 15;
        int e   = (idx >> 4) & 7;
        int pos = idx >> 7;
        int r = pos / 10, c = pos % 10;
        int h2 = h0 + r - 1, w2 = w0 + c - 1;
        u64 kv = 0, vv = 0;
        if (h2 >= 0 && h2 < 32 && w2 >= 0 && w2 < 32) {
            size_t gi = (((size_t)(n * 8 + e) * 1024) + h2 * 32 + w2) * 256
                        + m * 64 + d4 * 4;
            kv = *(const u64*)(k + gi);
            vv = *(const u64*)(v + gi);
        }
        int si = pos * HPS_H + e * EPS_H + d4 * 4;
        *(u64*)(sk + si) = kv;
        *(u64*)(sv + si) = vv;
    }
    for (int idx = t; idx < 2048; idx += 512) {
        int d4  = idx & 15;
        int gq  = (idx >> 4) & 7;
        int pix = idx >> 7;
        int p = (h0 + (pix >> 3)) * 32 + w0 + (pix & 7);
        size_t gi = (((size_t)(n * 8 + gq) * 1024) + p) * 256 + m * 64 + d4 * 4;
        *(u64*)(sq + pix * QPS_H + gq * EPS_H + d4 * 4) = *(const u64*)(q + gi);
    }
    for (int idx = t; idx < 768; idx += 512) {
        int d  = idx & 63;
        int ei = idx >> 6;
        int e  = ei / 3, i = ei % 3;
        srh[ei * EPS_H + d] = __float2half_rn(hm [((e * 256 + m * 64 + d) * 3) + i]);
        srw[ei * EPS_H + d] = __float2half_rn(wmm[((e * 256 + m * 64 + d) * 3) + i]);
    }
    __syncthreads();

    int wi = t >> 5, l = t & 31;
    int g  = l >> 2, e0 = l & 3;
    int pr = wi >> 3, cc = (wi & 7) + 1;
    const __half* sqw = sq + wi * QPS_H + g * EPS_H;
    int eoff = e0 * EPS_H;

    int posoff[9];
#pragma unroll
    for (int i = 0; i < 3; i++)
#pragma unroll
        for (int j = 0; j < 3; j++)
            posoff[i * 3 + j] = ((pr + i) * 10 + cc - 1 + j) * HPS_H;

    __half2 z2 = __float2half2_rn(0.f);

    // ---- q . rel (separate loop, R15 config) ----
    __half2 hA2[3], hB2[3];
#pragma unroll
    for (int u = 0; u < 3; u++) { hA2[u] = z2; hB2[u] = z2; }
#pragma unroll
    for (int d8 = 0; d8 < 8; d8++) {
        int dd = d8 * 8;
        uint4 qv = *(const uint4*)(sqw + dd);
#pragma unroll
        for (int u = 0; u < 3; u++) {
            uint4 r4 = *(const uint4*)(srh + (e0 * 3 + u) * EPS_H + dd);
            uint4 s4 = *(const uint4*)(srw + (e0 * 3 + u) * EPS_H + dd);
            hA2[u] = __hfma2(h2u(qv.x), h2u(r4.x), hA2[u]);
            hA2[u] = __hfma2(h2u(qv.y), h2u(r4.y), hA2[u]);
            hA2[u] = __hfma2(h2u(qv.z), h2u(r4.z), hA2[u]);
            hA2[u] = __hfma2(h2u(qv.w), h2u(r4.w), hA2[u]);
            hB2[u] = __hfma2(h2u(qv.x), h2u(s4.x), hB2[u]);
            hB2[u] = __hfma2(h2u(qv.y), h2u(s4.y), hB2[u]);
            hB2[u] = __hfma2(h2u(qv.z), h2u(s4.z), hB2[u]);
            hB2[u] = __hfma2(h2u(qv.w), h2u(s4.w), hB2[u]);
        }
    }
    float qrA[3], qrB[3];
#pragma unroll
    for (int u = 0; u < 3; u++) {
        float2 fa = __half22float2(hA2[u]), fb = __half22float2(hB2[u]);
        qrA[u] = fa.x + fa.y; qrB[u] = fb.x + fb.y;
    }

    // ---- scores (separate loop, R15 config) ----
    __half2 cA2[9], cB2[9];
#pragma unroll
    for (int u = 0; u < 9; u++) { cA2[u] = z2; cB2[u] = z2; }
#pragma unroll
    for (int d8 = 0; d8 < 8; d8++) {
        int dd = d8 * 8;
        uint4 qv = *(const uint4*)(sqw + dd);
#pragma unroll
        for (int u = 0; u < 9; u++) {
            const __half* kp = sk + posoff[u] + eoff + dd;
            uint4 ka = *(const uint4*)(kp);
            uint4 kc = *(const uint4*)(kp + 4 * EPS_H);
            cA2[u] = __hfma2(h2u(qv.x), h2u(ka.x), cA2[u]);
            cA2[u] = __hfma2(h2u(qv.y), h2u(ka.y), cA2[u]);
            cA2[u] = __hfma2(h2u(qv.z), h2u(ka.z), cA2[u]);
            cA2[u] = __hfma2(h2u(qv.w), h2u(ka.w), cA2[u]);
            cB2[u] = __hfma2(h2u(qv.x), h2u(kc.x), cB2[u]);
            cB2[u] = __hfma2(h2u(qv.y), h2u(kc.y), cB2[u]);
            cB2[u] = __hfma2(h2u(qv.z), h2u(kc.z), cB2[u]);
            cB2[u] = __hfma2(h2u(qv.w), h2u(kc.w), cB2[u]);
        }
    }
    float sA[9], sB[9];
#pragma unroll
    for (int u = 0; u < 9; u++) {
        float2 fa = __half22float2(cA2[u]), fb = __half22float2(cB2[u]);
        sA[u] = fa.x + fa.y + qrA[u / 3];
        sB[u] = fb.x + fb.y + qrB[u % 3];
    }

    float mx = -1e30f;
#pragma unroll
    for (int u = 0; u < 9; u++) mx = fmaxf(mx, fmaxf(sA[u], sB[u]));
    mx = fmaxf(mx, __shfl_xor_sync(0xffffffffu, mx, 1));
    mx = fmaxf(mx, __shfl_xor_sync(0xffffffffu, mx, 2));
    float sum = 0.f;
#pragma unroll
    for (int u = 0; u < 9; u++) {
        sA[u] = __expf(sA[u] - mx);
        sB[u] = __expf(sB[u] - mx);
        sum += sA[u] + sB[u];
    }
    sum += __shfl_xor_sync(0xffffffffu, sum, 1);
    sum += __shfl_xor_sync(0xffffffffu, sum, 2);
    float inv = 1.f / sum;

    __syncthreads();   // all warps done reading sk (k) before attd overlay

    __half2* awT = attd + wi * 576;
#pragma unroll
    for (int u = 0; u < 9; u++) {
        awT[((e0 * 9 + u) * 8 + g)]       = __float2half2_rn(sA[u] * inv);
        awT[(((e0 + 4) * 9 + u) * 8 + g)] = __float2half2_rn(sB[u] * inv);
    }
    __syncwarp();

    __half2 acc2[8];
#pragma unroll
    for (int gg = 0; gg < 8; gg++) acc2[gg] = z2;
#pragma unroll 1
    for (int e = 0; e < 8; e++) {
        const __half* vb = sv + e * EPS_H + 2 * l;
#pragma unroll
        for (int nb = 0; nb < 9; nb++) {
            __half2 v2 = *(const __half2*)(vb + posoff[nb]);
            const uint4* wp2 = (const uint4*)(awT + (e * 9 + nb) * 8);
            uint4 wa = wp2[0], wb = wp2[1];
            acc2[0] = __hfma2(h2u(wa.x), v2, acc2[0]);
            acc2[1] = __hfma2(h2u(wa.y), v2, acc2[1]);
            acc2[2] = __hfma2(h2u(wa.z), v2, acc2[2]);
            acc2[3] = __hfma2(h2u(wa.w), v2, acc2[3]);
            acc2[4] = __hfma2(h2u(wb.x), v2, acc2[4]);
            acc2[5] = __hfma2(h2u(wb.y), v2, acc2[5]);
            acc2[6] = __hfma2(h2u(wb.z), v2, acc2[6]);
            acc2[7] = __hfma2(h2u(wb.w), v2, acc2[7]);
        }
    }

    // ---- direct coalesced store: per g, warp covers 128 contiguous bytes ----
    {
        int p = (h0 + (wi >> 3)) * 32 + w0 + (wi & 7);
        __half* ob = avhT + (((size_t)(n * 8) * 1024) + p) * 256 + m * 64 + 2 * l;
#pragma unroll
        for (int gg = 0; gg < 8; gg++)
            *(__half2*)(ob + (size_t)gg * 262144) = acc2[gg];
    }
}

// ---------------------------------------------------------------------------
extern "C" void kernel_launch(void* const* d_in, const int* in_sizes, int n_in,
                              void* d_out, int out_size)
{
    (void)in_sizes; (void)n_in; (void)out_size;
    const float* x     = (const float*)d_in[0];
    const float* wq    = (const float*)d_in[1];
    const float* wk    = (const float*)d_in[2];
    const float* wv    = (const float*)d_in[3];
    const float* hm    = (const float*)d_in[4];
    const float* wm    = (const float*)d_in[5];
    const float* wconv = (const float*)d_in[6];
    const float* bconv = (const float*)d_in[7];
    const float* wf1   = (const float*)d_in[8];
    const float* bf1   = (const float*)d_in[9];
    const float* wf2   = (const float*)d_in[10];
    const float* bf2   = (const float*)d_in[11];
    const float* g1    = (const float*)d_in[12];
    const float* b1    = (const float*)d_in[13];
    const float* g2    = (const float*)d_in[14];
    const float* b2    = (const float*)d_in[15];

    __half *qkvh, *xhT, *xh2, *whi;
    cudaGetSymbolAddress((void**)&qkvh, g_qkv);
    cudaGetSymbolAddress((void**)&xhT,  g_xhT);
    cudaGetSymbolAddress((void**)&xh2,  g_xh2);
    cudaGetSymbolAddress((void**)&whi,  g_whi);

    cudaFuncSetAttribute(attn_kernel,
                         cudaFuncAttributeMaxDynamicSharedMemorySize, ATTN_SMEM_B);
    const int GEMM_SMEM = 98304;
    cudaFuncSetAttribute(hgemm_kernel,
                         cudaFuncAttributeMaxDynamicSharedMemorySize, GEMM_SMEM);

    const size_t WS = 524288;        // per-slot W elements
    const size_t QS = 8388608;       // per-slot qkv halves

    // fused weight-convert (slot4 k-permuted) + x transpose-convert
    prep_kernel<<<11264, 256>>>(wq, wk, wv, wconv, wf1, wf2, whi, x, xhT);

    // fused q/k/v GEMM -> fp16 transposed [bz][p][c] per slot
    hgemm_kernel<<<dim3(8, 6, 32), 256, GEMM_SMEM>>>(whi, xhT, nullptr,
        nullptr, qkvh, nullptr, nullptr, nullptr, 2, 0);

    attn_kernel<<<dim3(4, 16, 16), 512, ATTN_SMEM_B>>>(qkvh, qkvh + QS, qkvh + 2 * QS,
                                                       hm, wm, xhT);

    // w_conv GEMM: skip(x)+LN1 -> fp16 k-permuted tbh (into qkv slot 0)
    hgemm_kernel<<<dim3(8, 2, 32), 256, GEMM_SMEM>>>(whi + 3*WS, xhT, bconv,
        nullptr, qkvh, x, g1, b1, 4, 0);

    // f1 GEMM (relu, permuted weights) reads tbh -> fp16 transposed xh2
    hgemm_kernel<<<dim3(8, 2, 32), 256, GEMM_SMEM>>>(whi + 4*WS, qkvh, bf1,
        nullptr, xh2, nullptr, nullptr, nullptr, 2, 1);

    // f2 GEMM: skip(tbh fp16)+LN2 -> scrambled fp32 d_out
    hgemm_kernel<<<dim3(8, 2, 32), 256, GEMM_SMEM>>>(whi + 5*WS, xh2, bf2,
        (float*)d_out, qkvh, nullptr, g2, b2, 5, 0);
}